// round 4
// baseline (speedup 1.0000x reference)
#include <cuda_runtime.h>
#include <cuda_bf16.h>
#include <stdint.h>

// Problem constants
#define Nn    30000
#define Rr    8
#define NB    30
#define INDIM 256
#define ZDIM  128
#define HIDD  256
#define NE    (Nn * 16)          // 480000
#define NSEG  (Nn * Rr)          // 240000
#define KTOT  2304               // 2048 (aggregated, R*256) + 256 (root input)

// -------- scratch (device globals; no runtime allocation allowed) --------
__device__ float g_Ws1[2048 * 256];     // stacked W1: [(r*256+i), o]
__device__ float g_Ws2[2048 * 128];     // stacked W2
__device__ int   g_cnt[NSEG];
__device__ int   g_offs[NSEG + 1];
__device__ int   g_cursor[NSEG];
__device__ int   g_bsums[128];
__device__ int   g_sorted[NE];          // src node id, sorted by segment
__device__ float g_M[(size_t)Nn * 2048];   // aggregated means, reused by both layers
__device__ float g_z1[(size_t)Nn * 256];   // layer-1 output (post leaky-relu)

// ---------------- W build: Ws[(r*IN+i)*OUT+o] = sum_b comp[r,b]*bases[b,i,o] ----
template<int LAYER>
__global__ void build_W(const float* __restrict__ bases, const float* __restrict__ comp) {
    const int indim = 256;
    const int outd = (LAYER == 1) ? 256 : 128;
    float* Wout = (LAYER == 1) ? g_Ws1 : g_Ws2;
    int idx = blockIdx.x * blockDim.x + threadIdx.x;
    int total = Rr * indim * outd;
    if (idx >= total) return;
    int o = idx % outd;
    int i = (idx / outd) % indim;
    int r = idx / (outd * indim);
    float s = 0.f;
#pragma unroll
    for (int b = 0; b < NB; b++)
        s += comp[r * NB + b] * bases[((size_t)b * indim + i) * outd + o];
    Wout[idx] = s;
}

// ---------------- edge histogram / counting sort ----------------
__global__ void zero_cnt() {
    int i = blockIdx.x * blockDim.x + threadIdx.x;
    if (i < NSEG) g_cnt[i] = 0;
}

__global__ void hist(const int* __restrict__ ei, const int* __restrict__ et) {
    int e = blockIdx.x * blockDim.x + threadIdx.x;
    if (e >= NE) return;
    int dst = ei[NE + e];
    int r   = et[e];
    if ((unsigned)dst < (unsigned)Nn && (unsigned)r < (unsigned)Rr)
        atomicAdd(&g_cnt[dst * Rr + r], 1);
}

// block-wise scan: 512 threads * 4 elems = 2048/block ; 118 blocks
__global__ void scan1() {
    __shared__ int sh[512];
    int t = threadIdx.x;
    int base = blockIdx.x * 2048 + t * 4;
    int v[4];
    int s = 0;
#pragma unroll
    for (int j = 0; j < 4; j++) {
        int id = base + j;
        v[j] = (id < NSEG) ? g_cnt[id] : 0;
        s += v[j];
    }
    sh[t] = s;
    __syncthreads();
    for (int o = 1; o < 512; o <<= 1) {
        int u = (t >= o) ? sh[t - o] : 0;
        __syncthreads();
        sh[t] += u;
        __syncthreads();
    }
    if (t == 511) g_bsums[blockIdx.x] = sh[511];
    int ex = sh[t] - s;
#pragma unroll
    for (int j = 0; j < 4; j++) {
        int id = base + j;
        if (id < NSEG) g_offs[id] = ex;
        ex += v[j];
    }
}

__global__ void scan2(int nb) {
    if (threadIdx.x == 0) {
        int run = 0;
        for (int i = 0; i < nb; i++) { int c = g_bsums[i]; g_bsums[i] = run; run += c; }
    }
}

__global__ void scan3() {
    int id = blockIdx.x * blockDim.x + threadIdx.x;
    if (id < NSEG) {
        int v = g_offs[id] + g_bsums[id >> 11];
        g_offs[id] = v;
        g_cursor[id] = v;
    }
    if (id == 0) g_offs[NSEG] = NE;
}

__global__ void scatter(const int* __restrict__ ei, const int* __restrict__ et) {
    int e = blockIdx.x * blockDim.x + threadIdx.x;
    if (e >= NE) return;
    int src = ei[e];
    int dst = ei[NE + e];
    int r   = et[e];
    if ((unsigned)src >= (unsigned)Nn || (unsigned)dst >= (unsigned)Nn ||
        (unsigned)r >= (unsigned)Rr) return;
    int seg = dst * Rr + r;
    int pos = atomicAdd(&g_cursor[seg], 1);
    if ((unsigned)pos < (unsigned)NE) g_sorted[pos] = src;
}

// ---------------- segment-mean aggregation: one warp per (dst, r) ----------------
// writes g_M[dst*2048 + r*256 + :] = mean of feat[src] over segment edges (0 if empty)
template<int LAYER>
__global__ void aggregate(const float* __restrict__ xarg) {
    const float* feat = (LAYER == 1) ? xarg : (const float*)g_z1;
    int warp = (blockIdx.x * blockDim.x + threadIdx.x) >> 5;
    int lane = threadIdx.x & 31;
    if (warp >= NSEG) return;
    int begin = g_offs[warp];
    int end   = g_offs[warp + 1];
    float4 a0 = make_float4(0.f, 0.f, 0.f, 0.f);
    float4 a1 = make_float4(0.f, 0.f, 0.f, 0.f);
    for (int j = begin; j < end; j++) {
        int src = g_sorted[j];
        const float4* p = (const float4*)(feat + (size_t)src * 256);
        float4 u = p[lane];
        float4 w = p[lane + 32];
        a0.x += u.x; a0.y += u.y; a0.z += u.z; a0.w += u.w;
        a1.x += w.x; a1.y += w.y; a1.z += w.z; a1.w += w.w;
    }
    float inv = (end > begin) ? 1.f / (float)(end - begin) : 0.f;
    a0.x *= inv; a0.y *= inv; a0.z *= inv; a0.w *= inv;
    a1.x *= inv; a1.y *= inv; a1.z *= inv; a1.w *= inv;
    int dst = warp >> 3, r = warp & 7;
    float4* o = (float4*)(g_M + (size_t)dst * 2048 + r * 256);
    o[lane] = a0;
    o[lane + 32] = a1;
}

// ---------------- fused GEMM ----------------
// C[N, OUTD] = act( [g_M | F] @ [W ; root] + bias )
// A virtual [N, 2304]: cols 0..2047 from g_M, 2048..2303 from F.
// 128x128x16 tiles, 256 threads, 8x8 micro-tile per thread.
template<int OUTD, bool RELU, int LAYER>
__launch_bounds__(256, 2)
__global__ void gemm_fused(const float* __restrict__ xarg,
                           const float* __restrict__ root,
                           const float* __restrict__ bias,
                           float* __restrict__ Carg) {
    const float* F = (LAYER == 1) ? xarg : (const float*)g_z1;
    const float* W = (LAYER == 1) ? (const float*)g_Ws1 : (const float*)g_Ws2;
    float* C = (LAYER == 1) ? (float*)g_z1 : Carg;

    __shared__ float As[16][128];
    __shared__ float Bs[16][128];

    int tid = threadIdx.x;
    int tx = tid & 15, ty = tid >> 4;
    int row0 = blockIdx.x * 128;
    int col0 = blockIdx.y * 128;

    float acc[8][8];
#pragma unroll
    for (int i = 0; i < 8; i++)
#pragma unroll
        for (int j = 0; j < 8; j++) acc[i][j] = 0.f;

    for (int k0 = 0; k0 < KTOT; k0 += 16) {
#pragma unroll
        for (int u = 0; u < 2; u++) {
            int idx = tid + u * 256;
            // ---- A tile (128 rows x 16 k), stored transposed As[k][m]
            int ar = idx >> 2;
            int ak = (idx & 3) * 4;
            int grow = row0 + ar;
            float4 av = make_float4(0.f, 0.f, 0.f, 0.f);
            if (grow < Nn) {
                int kk = k0 + ak;
                const float* srcp = (kk < 2048)
                    ? (g_M + (size_t)grow * 2048 + kk)
                    : (F + (size_t)grow * 256 + (kk - 2048));
                av = *(const float4*)srcp;
            }
            As[ak + 0][ar] = av.x;
            As[ak + 1][ar] = av.y;
            As[ak + 2][ar] = av.z;
            As[ak + 3][ar] = av.w;
            // ---- B tile (16 k x 128 cols)
            int bk = idx >> 5;
            int bn = (idx & 31) * 4;
            int kk2 = k0 + bk;
            const float* bsrc = (kk2 < 2048)
                ? (W + (size_t)kk2 * OUTD + col0 + bn)
                : (root + (size_t)(kk2 - 2048) * OUTD + col0 + bn);
            *(float4*)&Bs[bk][bn] = *(const float4*)bsrc;
        }
        __syncthreads();
#pragma unroll
        for (int k = 0; k < 16; k++) {
            float4 a0 = *(const float4*)&As[k][ty * 4];
            float4 a1 = *(const float4*)&As[k][64 + ty * 4];
            float4 b0 = *(const float4*)&Bs[k][tx * 4];
            float4 b1 = *(const float4*)&Bs[k][64 + tx * 4];
            float ar8[8] = {a0.x, a0.y, a0.z, a0.w, a1.x, a1.y, a1.z, a1.w};
            float br8[8] = {b0.x, b0.y, b0.z, b0.w, b1.x, b1.y, b1.z, b1.w};
#pragma unroll
            for (int i = 0; i < 8; i++)
#pragma unroll
                for (int j = 0; j < 8; j++)
                    acc[i][j] += ar8[i] * br8[j];
        }
        __syncthreads();
    }

    // epilogue: bias + optional leaky-relu, vectorized stores
#pragma unroll
    for (int i = 0; i < 8; i++) {
        int r = row0 + ((i < 4) ? (ty * 4 + i) : (64 + ty * 4 + (i - 4)));
        if (r >= Nn) continue;
#pragma unroll
        for (int h = 0; h < 2; h++) {
            int cbase = col0 + ((h == 0) ? (tx * 4) : (64 + tx * 4));
            float4 v;
            float* vp = &v.x;
#pragma unroll
            for (int j = 0; j < 4; j++) {
                float t = acc[i][h * 4 + j] + bias[cbase + j];
                if (RELU) t = (t > 0.f) ? t : 0.01f * t;
                vp[j] = t;
            }
            *(float4*)(C + (size_t)r * OUTD + cbase) = v;
        }
    }
}

// ---------------- launch ----------------
extern "C" void kernel_launch(void* const* d_in, const int* in_sizes, int n_in,
                              void* d_out, int out_size) {
    const float* x      = (const float*)d_in[0];
    const int*   eidx   = (const int*)d_in[1];     // int32 [2, E]
    const int*   etype  = (const int*)d_in[2];     // int32 [E]
    const float* bases1 = (const float*)d_in[3];
    const float* comp1  = (const float*)d_in[4];
    const float* root1  = (const float*)d_in[5];
    const float* bias1  = (const float*)d_in[6];
    const float* bases2 = (const float*)d_in[7];
    const float* comp2  = (const float*)d_in[8];
    const float* root2  = (const float*)d_in[9];
    const float* bias2  = (const float*)d_in[10];
    float* out = (float*)d_out;

    // weights
    build_W<1><<<(Rr * 256 * 256 + 255) / 256, 256>>>(bases1, comp1);
    build_W<2><<<(Rr * 256 * 128 + 255) / 256, 256>>>(bases2, comp2);

    // counting sort of edges by segment (dst*R + rel)
    zero_cnt<<<(NSEG + 255) / 256, 256>>>();
    hist<<<(NE + 255) / 256, 256>>>(eidx, etype);
    int nb = (NSEG + 2047) / 2048;   // 118
    scan1<<<nb, 512>>>();
    scan2<<<1, 32>>>(nb);
    scan3<<<(NSEG + 255) / 256, 256>>>();
    scatter<<<(NE + 255) / 256, 256>>>(eidx, etype);

    // layer 1: aggregate means of x, fused GEMM (+root +bias, leaky relu) -> g_z1
    aggregate<1><<<NSEG / 8, 256>>>(x);
    gemm_fused<256, true, 1><<<dim3(235, 2), 256>>>(x, root1, bias1, nullptr);

    // layer 2: aggregate means of z1, fused GEMM -> out
    aggregate<2><<<NSEG / 8, 256>>>(x);
    gemm_fused<128, false, 2><<<dim3(235, 1), 256>>>(x, root2, bias2, out);
}

// round 6
// speedup vs baseline: 1.7980x; 1.7980x over previous
#include <cuda_runtime.h>
#include <cuda_bf16.h>
#include <stdint.h>

// Problem constants
#define Nn    30000
#define Rr    8
#define NB    30
#define NE    (Nn * 16)          // 480000
#define NSEG  (Nn * Rr)          // 240000
#define KTOT  2304               // 2048 (aggregated, R*256) + 256 (root input)

// -------- scratch (device globals) --------
__device__ float g_Wt1[256 * KTOT];     // W1^T : [o, k]
__device__ float g_Wt2[128 * KTOT];     // W2^T
__device__ int   g_cnt[NSEG];
__device__ int   g_offs[NSEG + 1];
__device__ int   g_cursor[NSEG];
__device__ int   g_bsums[128];
__device__ int   g_sorted[NE];
__device__ float g_M[(size_t)Nn * 2048];
__device__ float g_z1[(size_t)Nn * 256];

__device__ __forceinline__ uint32_t f2tf32(float f) {
    uint32_t u;
    asm("cvt.rna.tf32.f32 %0, %1;" : "=r"(u) : "f"(f));
    return u;
}

// ---------------- W^T build: Wt[o*2304 + k] ----------------
template<int LAYER>
__global__ void build_Wt(const float* __restrict__ bases, const float* __restrict__ comp,
                         const float* __restrict__ root) {
    const int outd = (LAYER == 1) ? 256 : 128;
    float* Wt = (LAYER == 1) ? g_Wt1 : g_Wt2;
    int idx = blockIdx.x * blockDim.x + threadIdx.x;
    if (idx >= outd * KTOT) return;
    int k = idx % KTOT;
    int o = idx / KTOT;
    float s;
    if (k < 2048) {
        int r = k >> 8, i = k & 255;
        s = 0.f;
#pragma unroll
        for (int b = 0; b < NB; b++)
            s += comp[r * NB + b] * bases[((size_t)b * 256 + i) * outd + o];
    } else {
        s = root[(size_t)(k - 2048) * outd + o];
    }
    Wt[idx] = s;
}

// ---------------- edge histogram / counting sort (unchanged, passing) ----------------
__global__ void zero_cnt() {
    int i = blockIdx.x * blockDim.x + threadIdx.x;
    if (i < NSEG) g_cnt[i] = 0;
}

__global__ void hist(const int* __restrict__ ei, const int* __restrict__ et) {
    int e = blockIdx.x * blockDim.x + threadIdx.x;
    if (e >= NE) return;
    int dst = ei[NE + e];
    int r   = et[e];
    if ((unsigned)dst < (unsigned)Nn && (unsigned)r < (unsigned)Rr)
        atomicAdd(&g_cnt[dst * Rr + r], 1);
}

__global__ void scan1() {
    __shared__ int sh[512];
    int t = threadIdx.x;
    int base = blockIdx.x * 2048 + t * 4;
    int v[4];
    int s = 0;
#pragma unroll
    for (int j = 0; j < 4; j++) {
        int id = base + j;
        v[j] = (id < NSEG) ? g_cnt[id] : 0;
        s += v[j];
    }
    sh[t] = s;
    __syncthreads();
    for (int o = 1; o < 512; o <<= 1) {
        int u = (t >= o) ? sh[t - o] : 0;
        __syncthreads();
        sh[t] += u;
        __syncthreads();
    }
    if (t == 511) g_bsums[blockIdx.x] = sh[511];
    int ex = sh[t] - s;
#pragma unroll
    for (int j = 0; j < 4; j++) {
        int id = base + j;
        if (id < NSEG) g_offs[id] = ex;
        ex += v[j];
    }
}

__global__ void scan2(int nb) {
    if (threadIdx.x == 0) {
        int run = 0;
        for (int i = 0; i < nb; i++) { int c = g_bsums[i]; g_bsums[i] = run; run += c; }
    }
}

__global__ void scan3() {
    int id = blockIdx.x * blockDim.x + threadIdx.x;
    if (id < NSEG) {
        int v = g_offs[id] + g_bsums[id >> 11];
        g_offs[id] = v;
        g_cursor[id] = v;
    }
    if (id == 0) g_offs[NSEG] = NE;
}

__global__ void scatter(const int* __restrict__ ei, const int* __restrict__ et) {
    int e = blockIdx.x * blockDim.x + threadIdx.x;
    if (e >= NE) return;
    int src = ei[e];
    int dst = ei[NE + e];
    int r   = et[e];
    if ((unsigned)src >= (unsigned)Nn || (unsigned)dst >= (unsigned)Nn ||
        (unsigned)r >= (unsigned)Rr) return;
    int seg = dst * Rr + r;
    int pos = atomicAdd(&g_cursor[seg], 1);
    if ((unsigned)pos < (unsigned)NE) g_sorted[pos] = src;
}

// ---------------- segment-mean aggregation (unchanged, passing) ----------------
template<int LAYER>
__global__ void aggregate(const float* __restrict__ xarg) {
    const float* feat = (LAYER == 1) ? xarg : (const float*)g_z1;
    int warp = (blockIdx.x * blockDim.x + threadIdx.x) >> 5;
    int lane = threadIdx.x & 31;
    if (warp >= NSEG) return;
    int begin = g_offs[warp];
    int end   = g_offs[warp + 1];
    float4 a0 = make_float4(0.f, 0.f, 0.f, 0.f);
    float4 a1 = make_float4(0.f, 0.f, 0.f, 0.f);
    for (int j = begin; j < end; j++) {
        int src = g_sorted[j];
        const float4* p = (const float4*)(feat + (size_t)src * 256);
        float4 u = p[lane];
        float4 w = p[lane + 32];
        a0.x += u.x; a0.y += u.y; a0.z += u.z; a0.w += u.w;
        a1.x += w.x; a1.y += w.y; a1.z += w.z; a1.w += w.w;
    }
    float inv = (end > begin) ? 1.f / (float)(end - begin) : 0.f;
    a0.x *= inv; a0.y *= inv; a0.z *= inv; a0.w *= inv;
    a1.x *= inv; a1.y *= inv; a1.z *= inv; a1.w *= inv;
    int dst = warp >> 3, r = warp & 7;
    float4* o = (float4*)(g_M + (size_t)dst * 2048 + r * 256);
    o[lane] = a0;
    o[lane + 32] = a1;
}

// ---------------- tf32 mma.sync fused GEMM ----------------
// C[:, col0:col0+128] = act( [g_M | F] @ Wt^T + bias )
// CTA tile 128(M) x 128(N), BK=32, 8 warps (2 m x 4 n), warp tile 64x32.
// m16n8k8 tf32 fragments; SMEM stride 36 floats (bank-conflict-free frag loads).
#define KSTRIDE 36
#define ABUF (128 * KSTRIDE)     // floats per buffer

template<int OUTD, bool RELU, int LAYER>
__launch_bounds__(256, 1)
__global__ void gemm_mma(const float* __restrict__ xarg,
                         const float* __restrict__ bias,
                         float* __restrict__ Carg) {
    const float* F  = (LAYER == 1) ? xarg : (const float*)g_z1;
    const float* Wt = (LAYER == 1) ? (const float*)g_Wt1 : (const float*)g_Wt2;
    float* C        = (LAYER == 1) ? (float*)g_z1 : Carg;

    extern __shared__ uint32_t smem[];
    uint32_t* As = smem;                 // [2][128][36]
    uint32_t* Bs = smem + 2 * ABUF;      // [2][128][36]

    const int tid = threadIdx.x;
    const int wid = tid >> 5, lane = tid & 31;
    const int mw = wid & 1, nw = wid >> 1;
    const int row0 = blockIdx.x * 128;
    const int col0 = blockIdx.y * 128;

    float acc[4][4][4];
#pragma unroll
    for (int i = 0; i < 4; i++)
#pragma unroll
        for (int j = 0; j < 4; j++)
#pragma unroll
            for (int q = 0; q < 4; q++) acc[i][j][q] = 0.f;

    const int r_ld = tid >> 3;           // base row (0..31), +32*u
    const int c4   = tid & 7;            // float4 column (k0 = c4*4)

    constexpr int NIT = KTOT / 32;       // 72

    float4 pa[4], pb[4];

    // ---- staging helpers (inline) ----
    auto ldg_tiles = [&](int it, float4* va, float4* vb) {
        int k0 = it * 32;
        const float* Abase;
        int rstride, kloc;
        if (k0 < 2048) { Abase = g_M; rstride = 2048; kloc = k0; }
        else           { Abase = F;   rstride = 256;  kloc = k0 - 2048; }
#pragma unroll
        for (int u = 0; u < 4; u++) {
            int r = u * 32 + r_ld;
            int grow = row0 + r;
            va[u] = make_float4(0.f, 0.f, 0.f, 0.f);
            if (grow < Nn)
                va[u] = *(const float4*)(Abase + (size_t)grow * rstride + kloc + c4 * 4);
            vb[u] = *(const float4*)(Wt + (size_t)(col0 + r) * KTOT + k0 + c4 * 4);
        }
    };
    auto sts_tiles = [&](int b, const float4* va, const float4* vb) {
        uint32_t* ab = As + b * ABUF;
        uint32_t* bb = Bs + b * ABUF;
#pragma unroll
        for (int u = 0; u < 4; u++) {
            int r = u * 32 + r_ld;
            uint4 ua, ub;
            ua.x = f2tf32(va[u].x); ua.y = f2tf32(va[u].y);
            ua.z = f2tf32(va[u].z); ua.w = f2tf32(va[u].w);
            ub.x = f2tf32(vb[u].x); ub.y = f2tf32(vb[u].y);
            ub.z = f2tf32(vb[u].z); ub.w = f2tf32(vb[u].w);
            *(uint4*)(ab + r * KSTRIDE + c4 * 4) = ua;
            *(uint4*)(bb + r * KSTRIDE + c4 * 4) = ub;
        }
    };

    // prologue
    ldg_tiles(0, pa, pb);
    sts_tiles(0, pa, pb);
    __syncthreads();

    const int lr = lane >> 2;            // 0..7
    const int lc = lane & 3;             // 0..3

    for (int it = 0; it < NIT; ++it) {
        if (it + 1 < NIT) ldg_tiles(it + 1, pa, pb);

        const uint32_t* ab = As + (it & 1) * ABUF + (mw * 64) * KSTRIDE;
        const uint32_t* bb = Bs + (it & 1) * ABUF + (nw * 32) * KSTRIDE;
#pragma unroll
        for (int kk = 0; kk < 4; kk++) {
            int k8 = kk * 8;
            uint32_t afr[4][4], bfr[4][2];
#pragma unroll
            for (int mt = 0; mt < 4; mt++) {
                const uint32_t* p = ab + (mt * 16 + lr) * KSTRIDE + k8 + lc;
                afr[mt][0] = p[0];
                afr[mt][1] = p[8 * KSTRIDE];
                afr[mt][2] = p[4];
                afr[mt][3] = p[8 * KSTRIDE + 4];
            }
#pragma unroll
            for (int nt = 0; nt < 4; nt++) {
                const uint32_t* p = bb + (nt * 8 + lr) * KSTRIDE + k8 + lc;
                bfr[nt][0] = p[0];
                bfr[nt][1] = p[4];
            }
#pragma unroll
            for (int mt = 0; mt < 4; mt++)
#pragma unroll
                for (int nt = 0; nt < 4; nt++) {
                    asm volatile(
                        "mma.sync.aligned.m16n8k8.row.col.f32.tf32.tf32.f32 "
                        "{%0,%1,%2,%3}, {%4,%5,%6,%7}, {%8,%9}, {%0,%1,%2,%3};"
                        : "+f"(acc[mt][nt][0]), "+f"(acc[mt][nt][1]),
                          "+f"(acc[mt][nt][2]), "+f"(acc[mt][nt][3])
                        : "r"(afr[mt][0]), "r"(afr[mt][1]), "r"(afr[mt][2]), "r"(afr[mt][3]),
                          "r"(bfr[nt][0]), "r"(bfr[nt][1]));
                }
        }
        __syncthreads();
        if (it + 1 < NIT) {
            sts_tiles((it + 1) & 1, pa, pb);
            __syncthreads();
        }
    }

    // ---- epilogue: bias + optional leaky-relu, float2 stores ----
#pragma unroll
    for (int mt = 0; mt < 4; mt++) {
        int m0 = row0 + mw * 64 + mt * 16 + lr;
#pragma unroll
        for (int nt = 0; nt < 4; nt++) {
            int cb = col0 + nw * 32 + nt * 8 + lc * 2;
            float b0 = bias[cb], b1 = bias[cb + 1];
            float v0 = acc[mt][nt][0] + b0;
            float v1 = acc[mt][nt][1] + b1;
            float v2 = acc[mt][nt][2] + b0;
            float v3 = acc[mt][nt][3] + b1;
            if (RELU) {
                v0 = (v0 > 0.f) ? v0 : 0.01f * v0;
                v1 = (v1 > 0.f) ? v1 : 0.01f * v1;
                v2 = (v2 > 0.f) ? v2 : 0.01f * v2;
                v3 = (v3 > 0.f) ? v3 : 0.01f * v3;
            }
            if (m0 < Nn)
                *(float2*)(C + (size_t)m0 * OUTD + cb) = make_float2(v0, v1);
            if (m0 + 8 < Nn)
                *(float2*)(C + (size_t)(m0 + 8) * OUTD + cb) = make_float2(v2, v3);
        }
    }
}

// ---------------- launch ----------------
extern "C" void kernel_launch(void* const* d_in, const int* in_sizes, int n_in,
                              void* d_out, int out_size) {
    const float* x      = (const float*)d_in[0];
    const int*   eidx   = (const int*)d_in[1];
    const int*   etype  = (const int*)d_in[2];
    const float* bases1 = (const float*)d_in[3];
    const float* comp1  = (const float*)d_in[4];
    const float* root1  = (const float*)d_in[5];
    const float* bias1  = (const float*)d_in[6];
    const float* bases2 = (const float*)d_in[7];
    const float* comp2  = (const float*)d_in[8];
    const float* root2  = (const float*)d_in[9];
    const float* bias2  = (const float*)d_in[10];
    float* out = (float*)d_out;

    const int smem_sz = 4 * ABUF * 4;    // 2 bufs x (A+B) x 128x36 u32 = 73728 B
    cudaFuncSetAttribute(gemm_mma<256, true, 1>,
                         cudaFuncAttributeMaxDynamicSharedMemorySize, smem_sz);
    cudaFuncSetAttribute(gemm_mma<128, false, 2>,
                         cudaFuncAttributeMaxDynamicSharedMemorySize, smem_sz);

    // weights (transposed, root appended)
    build_Wt<1><<<(256 * KTOT + 255) / 256, 256>>>(bases1, comp1, root1);
    build_Wt<2><<<(128 * KTOT + 255) / 256, 256>>>(bases2, comp2, root2);

    // counting sort of edges by segment (dst*R + rel)
    zero_cnt<<<(NSEG + 255) / 256, 256>>>();
    hist<<<(NE + 255) / 256, 256>>>(eidx, etype);
    int nb = (NSEG + 2047) / 2048;   // 118
    scan1<<<nb, 512>>>();
    scan2<<<1, 32>>>(nb);
    scan3<<<(NSEG + 255) / 256, 256>>>();
    scatter<<<(NE + 255) / 256, 256>>>(eidx, etype);

    // layer 1
    aggregate<1><<<NSEG / 8, 256>>>(x);
    gemm_mma<256, true, 1><<<dim3(235, 2), 256, smem_sz>>>(x, bias1, nullptr);

    // layer 2
    aggregate<2><<<NSEG / 8, 256>>>(x);
    gemm_mma<128, false, 2><<<dim3(235, 1), 256, smem_sz>>>(x, bias2, out);
}